// round 16
// baseline (speedup 1.0000x reference)
#include <cuda_runtime.h>
#include <cuda_bf16.h>
#include <cstdint>

#define T_LEN 512
#define NSTEP 511
#define BLK   256
#define GRID  128

__constant__ float cAc[6][5] = {
    {0.f,0.f,0.f,0.f,0.f},
    {0.161f,0.f,0.f,0.f,0.f},
    {-0.008480655492356989f,0.335480655492357f,0.f,0.f,0.f},
    {2.8971530571054935f,-6.359448489975075f,4.3622954328695815f,0.f,0.f},
    {5.325864828439257f,-11.748883564062828f,7.4955393428898365f,-0.09249506636175525f,0.f},
    {5.86145544294642f,-12.92096931784711f,8.159367898576159f,-0.071584973281401f,-0.028269050394068383f}
};
__constant__ float cBc[6] = {
    0.09646076681806523f,0.01f,0.4798896504144996f,
    1.379008574103742f,-3.290069515436081f,2.324710524099774f
};

// dt-folded transposed gradient planes: dqT[(n*3+c)*16384 + e]
__device__ float dqT[(size_t)NSTEP * 3 * 16384];
// pre-packed per-lane B fragments (192 tiles x 32 lanes x uint2)
__device__ uint2 gWpack[192 * 32];

// tile bases in gWpack
#define G1_HI 0     /* 16: n(0..7)*2 + k(0..1) */
#define G1_LO 16
#define G2_HI 32    /* 32: n(0..7)*4 + k(0..3) */
#define G2_LO 64
#define G3_HI 96    /* 48: (c(0..2)*4 + n(0..3))*4 + k(0..3) */
#define G3_LO 144

// SMEM: Wsm 49152 B + biases 896 B
#define SM_BIAS   49152
#define SMEM_BYTES (SM_BIAS + 224 * 4)

__device__ __forceinline__ uint32_t pack_bf16x2(float lo_f, float hi_f) {
    uint32_t r;
    asm("cvt.rn.bf16x2.f32 %0, %1, %2;" : "=r"(r) : "f"(hi_f), "f"(lo_f));
    return r;
}
// split (v0,v1) -> hi pair + residual-lo pair (bf16x2 each, low half = v0)
__device__ __forceinline__ void split2(float v0, float v1, uint32_t& hi, uint32_t& lo) {
    asm("cvt.rn.bf16x2.f32 %0, %1, %2;" : "=r"(hi) : "f"(v1), "f"(v0));
    float h0 = __uint_as_float(hi << 16);
    float h1 = __uint_as_float(hi & 0xFFFF0000u);
    asm("cvt.rn.bf16x2.f32 %0, %1, %2;" : "=r"(lo) : "f"(v1 - h1), "f"(v0 - h0));
}
__device__ __forceinline__ void mma16816(float* c, const uint32_t* a, uint2 b) {
    asm volatile(
        "mma.sync.aligned.m16n8k16.row.col.f32.bf16.bf16.f32 "
        "{%0,%1,%2,%3}, {%4,%5,%6,%7}, {%8,%9}, {%0,%1,%2,%3};"
        : "+f"(c[0]), "+f"(c[1]), "+f"(c[2]), "+f"(c[3])
        : "r"(a[0]), "r"(a[1]), "r"(a[2]), "r"(a[3]), "r"(b.x), "r"(b.y));
}
__device__ __forceinline__ float tanh_fast(float x) {
    float e = __expf(2.0f * x);
    float r; asm("rcp.approx.f32 %0, %1;" : "=f"(r) : "f"(e + 1.0f));
    return fmaf(-2.0f, r, 1.0f);
}

// ---- prep: dq planes ----
__global__ void prep_dq(const float* __restrict__ grads, const float* __restrict__ times) {
    const int e = blockIdx.x * blockDim.x + threadIdx.x;
    const int t = blockIdx.y;
    const float dt = times[1] - times[0];
    const float* gp = grads + (size_t)e * T_LEN * 3 + t * 3;
    dqT[((size_t)t * 3 + 0) * 16384 + e] = gp[0] * dt;
    dqT[((size_t)t * 3 + 1) * 16384 + e] = gp[1] * dt;
    dqT[((size_t)t * 3 + 2) * 16384 + e] = gp[2] * dt;
}

// ---- prep: pack weights into per-lane mma B fragments (hi/lo split) ----
__global__ void prep_wpack(const float* __restrict__ w1,
                           const float* __restrict__ w2,
                           const float* __restrict__ w3)
{
    int t = blockIdx.x * blockDim.x + threadIdx.x;
    if (t >= 192 * 32) return;
    int tile = t >> 5, lane = t & 31;
    int gdx = lane >> 2, tig = lane & 3;
    int kk = 2 * tig;
    float v[4];
    bool lo;
    if (tile < 32) {                        // GEMM1: W1 [64][32]
        lo = tile >= 16; int tt = tile & 15;
        int nt = tt >> 1, kt = tt & 1;
        int r = nt * 8 + gdx, k0 = kt * 16 + kk;
        v[0] = w1[r * 32 + k0];     v[1] = w1[r * 32 + k0 + 1];
        v[2] = w1[r * 32 + k0 + 8]; v[3] = w1[r * 32 + k0 + 9];
    } else if (tile < 96) {                 // GEMM2: W2 [64][64]
        int tt = tile - 32; lo = tt >= 32; tt &= 31;
        int nt = tt >> 2, kt = tt & 3;
        int r = nt * 8 + gdx, k0 = kt * 16 + kk;
        v[0] = w2[r * 64 + k0];     v[1] = w2[r * 64 + k0 + 1];
        v[2] = w2[r * 64 + k0 + 8]; v[3] = w2[r * 64 + k0 + 9];
    } else {                                // GEMM3: W3_c[h][k] = w3[(3h+c)*64+k]
        int tt = tile - 96; lo = tt >= 48; tt %= 48;
        int c = tt >> 4, nt = (tt >> 2) & 3, kt = tt & 3;
        int h = nt * 8 + gdx, r = 3 * h + c, k0 = kt * 16 + kk;
        v[0] = w3[r * 64 + k0];     v[1] = w3[r * 64 + k0 + 1];
        v[2] = w3[r * 64 + k0 + 8]; v[3] = w3[r * 64 + k0 + 9];
    }
    if (lo) {
#pragma unroll
        for (int i = 0; i < 4; i++) {
            __nv_bfloat16 h = __float2bfloat16(v[i]);
            v[i] = v[i] - __bfloat162float(h);
        }
    }
    gWpack[t] = make_uint2(pack_bf16x2(v[0], v[1]), pack_bf16x2(v[2], v[3]));
}

__global__ void __launch_bounds__(BLK, 1)
neural_cde_mma(const float* __restrict__ b1g,
               const float* __restrict__ b2g,
               const float* __restrict__ b3g,
               const float* __restrict__ wencg,
               const float* __restrict__ bencg,
               const float* __restrict__ wrog,
               const float* __restrict__ brog,
               float* __restrict__ out)
{
    extern __shared__ char smem[];
    uint2* Wsm = (uint2*)smem;
    float* b1s = (float*)(smem + SM_BIAS);
    float* b2s = b1s + 64;
    float* b3s = b2s + 64;

    const int tid  = threadIdx.x;
    const int wid  = tid >> 5;
    const int lane = tid & 31;
    const int g    = lane >> 2;
    const int q    = lane & 3;

    for (int i = tid; i < 192 * 32; i += BLK) Wsm[i] = gWpack[i];
    for (int i = tid; i < 64; i += BLK) b1s[i] = b1g[i];
    for (int i = tid; i < 64; i += BLK) b2s[i] = b2g[i];
    for (int i = tid; i < 96; i += BLK) b3s[i] = b3g[i];
    __syncthreads();

    // state fragments: j = tn*4+cc -> (row = g + 8*(cc>>1), col = 8*tn + 2q + (cc&1))
    float z[16], k1[16], k2[16], k3[16], k4[16], k5[16], kv[16];
#pragma unroll
    for (int j = 0; j < 16; j++) {
        int col = 8 * (j >> 2) + 2 * q + (j & 1);
        z[j] = wencg[col] + bencg[col];
        k1[j] = k2[j] = k3[j] = k4[j] = k5[j] = 0.0f;
    }

    const int row0 = blockIdx.x * 128 + wid * 16 + g;   // element of rows g
    const int row1 = row0 + 8;                          // element of rows g+8

#pragma unroll 1
    for (int n = 0; n < NSTEP; n++) {
        float dqa[3], dqb[3];
#pragma unroll
        for (int c = 0; c < 3; c++) {
            dqa[c] = dqT[((size_t)n * 3 + c) * 16384 + row0];
            dqb[c] = dqT[((size_t)n * 3 + c) * 16384 + row1];
        }

#pragma unroll 1
        for (int s = 0; s < 6; s++) {
            // ---- y = z + sum A*k; split into A-frags (2 k-tiles) ----
            uint32_t yh[2][4], yl[2][4];
            {
                const float a0 = cAc[s][0], a1 = cAc[s][1], a2 = cAc[s][2];
                const float a3 = cAc[s][3], a4 = cAc[s][4];
                float y[16];
#pragma unroll
                for (int j = 0; j < 16; j++) {
                    float acc = z[j];
                    acc = fmaf(a0, k1[j], acc); acc = fmaf(a1, k2[j], acc);
                    acc = fmaf(a2, k3[j], acc); acc = fmaf(a3, k4[j], acc);
                    acc = fmaf(a4, k5[j], acc);
                    y[j] = acc;
                }
#pragma unroll
                for (int i = 0; i < 8; i++)
                    split2(y[2 * i], y[2 * i + 1], yh[i >> 2][i & 3], yl[i >> 2][i & 3]);
            }

            // ---- GEMM1: C[16x64] = y*W1^T (K=32), pass-ordered for ILP ----
            float C[32];
#pragma unroll
            for (int j = 0; j < 32; j++) C[j] = 0.0f;
#pragma unroll
            for (int k = 0; k < 2; k++) {
                uint2 bf[8];
#pragma unroll
                for (int nt = 0; nt < 8; nt++) bf[nt] = Wsm[(G1_HI + nt * 2 + k) * 32 + lane];
#pragma unroll
                for (int nt = 0; nt < 8; nt++) mma16816(C + 4 * nt, yh[k], bf[nt]);
#pragma unroll
                for (int nt = 0; nt < 8; nt++) mma16816(C + 4 * nt, yl[k], bf[nt]);
#pragma unroll
                for (int nt = 0; nt < 8; nt++) bf[nt] = Wsm[(G1_LO + nt * 2 + k) * 32 + lane];
#pragma unroll
                for (int nt = 0; nt < 8; nt++) mma16816(C + 4 * nt, yh[k], bf[nt]);
            }

            // ---- epi1: h1 = tanh(C + b1) -> A-frags (4 k-tiles) ----
            uint32_t ah[4][4], al[4][4];
#pragma unroll
            for (int i = 0; i < 16; i++) {
                float2 bias = *(float2*)(b1s + 8 * (i >> 1) + 2 * q);
                float t0 = tanh_fast(C[2 * i] + bias.x);
                float t1 = tanh_fast(C[2 * i + 1] + bias.y);
                split2(t0, t1, ah[i >> 2][i & 3], al[i >> 2][i & 3]);
            }

            // ---- GEMM2: C = h1*W2^T (K=64), pass-ordered ----
#pragma unroll
            for (int j = 0; j < 32; j++) C[j] = 0.0f;
#pragma unroll
            for (int k = 0; k < 4; k++) {
                uint2 bf[8];
#pragma unroll
                for (int nt = 0; nt < 8; nt++) bf[nt] = Wsm[(G2_HI + nt * 4 + k) * 32 + lane];
#pragma unroll
                for (int nt = 0; nt < 8; nt++) mma16816(C + 4 * nt, ah[k], bf[nt]);
#pragma unroll
                for (int nt = 0; nt < 8; nt++) mma16816(C + 4 * nt, al[k], bf[nt]);
#pragma unroll
                for (int nt = 0; nt < 8; nt++) bf[nt] = Wsm[(G2_LO + nt * 4 + k) * 32 + lane];
#pragma unroll
                for (int nt = 0; nt < 8; nt++) mma16816(C + 4 * nt, ah[k], bf[nt]);
            }

            // ---- epi2: h2 = tanh(C + b2) -> A-frags ----
#pragma unroll
            for (int i = 0; i < 16; i++) {
                float2 bias = *(float2*)(b2s + 8 * (i >> 1) + 2 * q);
                float t0 = tanh_fast(C[2 * i] + bias.x);
                float t1 = tanh_fast(C[2 * i + 1] + bias.y);
                split2(t0, t1, ah[i >> 2][i & 3], al[i >> 2][i & 3]);
            }

            // ---- GEMM3: all 3 channels in one 48-accumulator block ----
            float C3[48];
#pragma unroll
            for (int j = 0; j < 48; j++) C3[j] = 0.0f;
#pragma unroll
            for (int k = 0; k < 4; k++) {
                uint2 bf[12];
#pragma unroll
                for (int t = 0; t < 12; t++) bf[t] = Wsm[(G3_HI + t * 4 + k) * 32 + lane];
#pragma unroll
                for (int t = 0; t < 12; t++) mma16816(C3 + 4 * t, ah[k], bf[t]);
#pragma unroll
                for (int t = 0; t < 12; t++) mma16816(C3 + 4 * t, al[k], bf[t]);
#pragma unroll
                for (int t = 0; t < 12; t++) bf[t] = Wsm[(G3_LO + t * 4 + k) * 32 + lane];
#pragma unroll
                for (int t = 0; t < 12; t++) mma16816(C3 + 4 * t, ah[k], bf[t]);
            }

            // ---- dq contraction: kv[j] = sum_c (C3[c-tile] + b3) * dq_c ----
#pragma unroll
            for (int j = 0; j < 16; j++) kv[j] = 0.0f;
#pragma unroll
            for (int c = 0; c < 3; c++) {
                float dq_r0 = dqa[c], dq_r1 = dqb[c];
#pragma unroll
                for (int j = 0; j < 16; j++) {
                    int col = 8 * (j >> 2) + 2 * q + (j & 1);
                    float f = C3[(c * 4 + (j >> 2)) * 4 + (j & 3)] + b3s[3 * col + c];
                    kv[j] = fmaf(f, (j & 2) ? dq_r1 : dq_r0, kv[j]);
                }
            }

            if (s == 0) {
#pragma unroll
                for (int j = 0; j < 16; j++) k1[j] = kv[j];
            } else if (s == 1) {
#pragma unroll
                for (int j = 0; j < 16; j++) k2[j] = kv[j];
            } else if (s == 2) {
#pragma unroll
                for (int j = 0; j < 16; j++) k3[j] = kv[j];
            } else if (s == 3) {
#pragma unroll
                for (int j = 0; j < 16; j++) k4[j] = kv[j];
            } else if (s == 4) {
#pragma unroll
                for (int j = 0; j < 16; j++) k5[j] = kv[j];
            }
        } // stages

#pragma unroll
        for (int j = 0; j < 16; j++) {
            float acc = fmaf(cBc[5], kv[j], z[j]);
            acc = fmaf(cBc[0], k1[j], acc);
            acc = fmaf(cBc[1], k2[j], acc);
            acc = fmaf(cBc[2], k3[j], acc);
            acc = fmaf(cBc[3], k4[j], acc);
            acc = fmaf(cBc[4], k5[j], acc);
            z[j] = acc;
        }
    } // steps

    // ---- readout: per-row dot over quad, sigmoid ----
    {
        float pr0 = 0.0f, pr1 = 0.0f;
#pragma unroll
        for (int j = 0; j < 16; j++) {
            int col = 8 * (j >> 2) + 2 * q + (j & 1);
            float wr = wrog[col];
            if (j & 2) pr1 = fmaf(z[j], wr, pr1);
            else       pr0 = fmaf(z[j], wr, pr0);
        }
        pr0 += __shfl_xor_sync(0xFFFFFFFFu, pr0, 1);
        pr0 += __shfl_xor_sync(0xFFFFFFFFu, pr0, 2);
        pr1 += __shfl_xor_sync(0xFFFFFFFFu, pr1, 1);
        pr1 += __shfl_xor_sync(0xFFFFFFFFu, pr1, 2);
        if (q == 0) {
            float b0 = brog[0];
            out[row0] = __fdividef(1.0f, 1.0f + __expf(-(pr0 + b0)));
            out[row1] = __fdividef(1.0f, 1.0f + __expf(-(pr1 + b0)));
        }
    }
}

extern "C" void kernel_launch(void* const* d_in, const int* in_sizes, int n_in,
                              void* d_out, int out_size)
{
    const float* times = (const float*)d_in[0];
    const float* grads = (const float*)d_in[1];
    const float* w1    = (const float*)d_in[2];
    const float* b1    = (const float*)d_in[3];
    const float* w2    = (const float*)d_in[4];
    const float* b2    = (const float*)d_in[5];
    const float* w3    = (const float*)d_in[6];
    const float* b3    = (const float*)d_in[7];
    const float* wenc  = (const float*)d_in[8];
    const float* benc  = (const float*)d_in[9];
    const float* wro   = (const float*)d_in[10];
    const float* bro   = (const float*)d_in[11];
    float* out = (float*)d_out;

    dim3 pgrid(16384 / 256, NSTEP);
    prep_dq<<<pgrid, 256>>>(grads, times);
    prep_wpack<<<24, 256>>>(w1, w2, w3);

    cudaFuncSetAttribute(neural_cde_mma,
                         cudaFuncAttributeMaxDynamicSharedMemorySize, SMEM_BYTES);
    neural_cde_mma<<<GRID, BLK, SMEM_BYTES>>>(
        b1, b2, b3, wenc, benc, wro, bro, out);
}